// round 12
// baseline (speedup 1.0000x reference)
#include <cuda_runtime.h>
#include <cuda_fp16.h>
#include <math.h>
#include <float.h>

#define N_NODES 100000
#define N_EDGES 1600000
#define ETOT    (N_EDGES + N_NODES)
#define IN_DIM  256
#define HID     128
#define OUTD    64
#define NEG_SLOPE 0.2f
#define SCAN_NB ((N_NODES + 255) / 256)   // 391
#define FULLM 0xffffffffu

// ---------------- scratch (static device globals; no allocation) ----------------
// Placement law (measured R4/R9/R10): random gathers from statics ~200 GB/s;
// gathers from d_out are device-fast; streams are fast everywhere.
static __device__ __align__(128) float g_o1[(size_t)N_NODES * HID];   // elu(agg1+b1), streamed
static __device__ __align__(128) float g_o2[(size_t)N_NODES * OUTD];  // staged final, streamed
static __device__ float g_ssrc[N_NODES];
static __device__ float g_sdst[N_NODES];
static __device__ int   g_cnt[N_NODES];
static __device__ int   g_cur[N_NODES];
static __device__ int   g_off[N_NODES + 1];
static __device__ int   g_bsum[512];
static __device__ int   g_col[ETOT];

// ---------------- CSR build (verbatim, verified) ----------------
__global__ void k_zeroA() {
    int i = blockIdx.x * blockDim.x + threadIdx.x;
    if (i < N_NODES) g_cnt[i] = 0;
}
__global__ void k_zeroB() {
    int i = blockIdx.x * blockDim.x + threadIdx.x;
    if (i < N_NODES) g_cur[i] = 0;
}

__global__ void k_count(const int* __restrict__ ei) {
    int t = blockIdx.x * blockDim.x + threadIdx.x;
    if (t >= ETOT) return;
    int dst = (t < N_EDGES) ? ei[N_EDGES + t] : (t - N_EDGES);
    atomicAdd(&g_cnt[dst], 1);
}

__global__ void k_scan1() {
    __shared__ int s[256];
    int t = threadIdx.x, idx = blockIdx.x * 256 + t;
    int v = (idx < N_NODES) ? g_cnt[idx] : 0;
    s[t] = v; __syncthreads();
    #pragma unroll
    for (int o = 1; o < 256; o <<= 1) {
        int u = (t >= o) ? s[t - o] : 0;
        __syncthreads();
        s[t] += u;
        __syncthreads();
    }
    if (idx < N_NODES) g_off[idx] = s[t] - v;
    if (t == 255) g_bsum[blockIdx.x] = s[t];
}

__global__ void k_scan2(int nb) {
    __shared__ int s[512];
    int t = threadIdx.x;
    int v = (t < nb) ? g_bsum[t] : 0;
    s[t] = v; __syncthreads();
    #pragma unroll
    for (int o = 1; o < 512; o <<= 1) {
        int u = (t >= o) ? s[t - o] : 0;
        __syncthreads();
        s[t] += u;
        __syncthreads();
    }
    g_bsum[t] = s[t] - v;
}

__global__ void k_scan3() {
    int t = threadIdx.x, idx = blockIdx.x * 256 + t;
    if (idx < N_NODES) g_off[idx] += g_bsum[blockIdx.x];
    if (idx == 0) g_off[N_NODES] = ETOT;
}

__global__ void k_fill(const int* __restrict__ ei) {
    int t = blockIdx.x * blockDim.x + threadIdx.x;
    if (t >= ETOT) return;
    int src, dst;
    if (t < N_EDGES) { src = ei[t]; dst = ei[N_EDGES + t]; }
    else             { src = dst = t - N_EDGES; }
    int pos = g_off[dst] + atomicAdd(&g_cur[dst], 1);
    g_col[pos] = src;
}

// ---------------- tensor-core GEMM1 (verbatim from R11, verified) ----------------
__global__ void __launch_bounds__(256) k_gemm1_mma(
        const float* __restrict__ A, const float* __restrict__ W,
        __half* __restrict__ Hout,
        const float* __restrict__ asrc, const float* __restrict__ adst,
        float* __restrict__ ssrc, float* __restrict__ sdst, int M) {
    constexpr int BM = 64;
    __shared__ __half As[BM][24];
    __shared__ __half Bs[128][20];
    __shared__ __half Hs[BM][136];

    const int tid = threadIdx.x;
    const int w   = tid >> 5;
    const int lane = tid & 31;
    const int g = lane >> 2;
    const int t = lane & 3;
    const int wm = (w & 1) * 32;
    const int wn = (w >> 1) * 32;
    const int m0 = blockIdx.x * BM;

    float c[2][4][4];
    #pragma unroll
    for (int mf = 0; mf < 2; mf++)
        #pragma unroll
        for (int nf = 0; nf < 4; nf++)
            #pragma unroll
            for (int q = 0; q < 4; q++) c[mf][nf][q] = 0.f;

    const int arow = tid >> 2;
    const int ac4  = (tid & 3) * 4;

    for (int k0 = 0; k0 < IN_DIM; k0 += 16) {
        {
            float4 v = make_float4(0.f, 0.f, 0.f, 0.f);
            int gr = m0 + arow;
            if (gr < M) v = *(const float4*)(A + (size_t)gr * IN_DIM + k0 + ac4);
            *(__half2*)&As[arow][ac4]     = __floats2half2_rn(v.x, v.y);
            *(__half2*)&As[arow][ac4 + 2] = __floats2half2_rn(v.z, v.w);
        }
        #pragma unroll
        for (int i = tid; i < 16 * 32; i += 256) {
            int kk = i >> 5;
            int n4 = (i & 31) * 4;
            float4 wv = *(const float4*)(W + (size_t)(k0 + kk) * HID + n4);
            Bs[n4 + 0][kk] = __float2half_rn(wv.x);
            Bs[n4 + 1][kk] = __float2half_rn(wv.y);
            Bs[n4 + 2][kk] = __float2half_rn(wv.z);
            Bs[n4 + 3][kk] = __float2half_rn(wv.w);
        }
        __syncthreads();

        unsigned a[2][4];
        #pragma unroll
        for (int mf = 0; mf < 2; mf++) {
            int r = wm + mf * 16;
            a[mf][0] = *(const unsigned*)&As[r + g][2 * t];
            a[mf][1] = *(const unsigned*)&As[r + 8 + g][2 * t];
            a[mf][2] = *(const unsigned*)&As[r + g][2 * t + 8];
            a[mf][3] = *(const unsigned*)&As[r + 8 + g][2 * t + 8];
        }
        #pragma unroll
        for (int nf = 0; nf < 4; nf++) {
            int n = wn + nf * 8;
            unsigned b0 = *(const unsigned*)&Bs[n + g][2 * t];
            unsigned b1 = *(const unsigned*)&Bs[n + g][2 * t + 8];
            #pragma unroll
            for (int mf = 0; mf < 2; mf++) {
                asm volatile(
                    "mma.sync.aligned.m16n8k16.row.col.f32.f16.f16.f32 "
                    "{%0,%1,%2,%3}, {%4,%5,%6,%7}, {%8,%9}, {%0,%1,%2,%3};"
                    : "+f"(c[mf][nf][0]), "+f"(c[mf][nf][1]),
                      "+f"(c[mf][nf][2]), "+f"(c[mf][nf][3])
                    : "r"(a[mf][0]), "r"(a[mf][1]), "r"(a[mf][2]), "r"(a[mf][3]),
                      "r"(b0), "r"(b1));
            }
        }
        __syncthreads();
    }

    #pragma unroll
    for (int mf = 0; mf < 2; mf++) {
        #pragma unroll
        for (int nf = 0; nf < 4; nf++) {
            int r0 = wm + mf * 16 + g;
            int cc = wn + nf * 8 + 2 * t;
            *(__half2*)&Hs[r0][cc]     = __floats2half2_rn(c[mf][nf][0], c[mf][nf][1]);
            *(__half2*)&Hs[r0 + 8][cc] = __floats2half2_rn(c[mf][nf][2], c[mf][nf][3]);
        }
    }
    __syncthreads();

    #pragma unroll
    for (int i = tid; i < 64 * 16; i += 256) {
        int row = i >> 4, seg = i & 15;
        if (m0 + row < M) {
            uint4 v = *(const uint4*)&Hs[row][seg * 8];
            *(uint4*)(Hout + (size_t)(m0 + row) * HID + seg * 8) = v;
        }
    }

    float4 a1v = *(const float4*)(asrc + lane * 4);
    float4 a2v = *(const float4*)(adst + lane * 4);
    #pragma unroll
    for (int r = 0; r < 8; r++) {
        int row = w * 8 + r;
        uint2 hv = *(const uint2*)&Hs[row][lane * 4];
        const __half* hp = reinterpret_cast<const __half*>(&hv);
        float f0 = __half2float(hp[0]), f1 = __half2float(hp[1]);
        float f2 = __half2float(hp[2]), f3 = __half2float(hp[3]);
        float d1 = f0 * a1v.x + f1 * a1v.y + f2 * a1v.z + f3 * a1v.w;
        float d2 = f0 * a2v.x + f1 * a2v.y + f2 * a2v.z + f3 * a2v.w;
        #pragma unroll
        for (int o = 16; o; o >>= 1) {
            d1 += __shfl_xor_sync(FULLM, d1, o);
            d2 += __shfl_xor_sync(FULLM, d2, o);
        }
        if (lane == 0 && m0 + row < M) {
            ssrc[m0 + row] = d1;
            sdst[m0 + row] = d2;
        }
    }
}

// ---------------- NEW: tensor-core GEMM2 (fp16 in, fp32 acc, fp32 out) ----------------
// h2[M,64] = o1[M,128] @ W2[128,64]; fp32 h2 to d_out; fused score epilogue.
// BM=64, BN=64, k-step 16 (8 steps). 8 warps = 4(m) x 2(n); warp tile 16x32.
__global__ void __launch_bounds__(256) k_gemm2_mma(
        const float* __restrict__ A, const float* __restrict__ W,
        float* __restrict__ Hout,
        const float* __restrict__ asrc, const float* __restrict__ adst,
        float* __restrict__ ssrc, float* __restrict__ sdst, int M) {
    constexpr int BM = 64;
    __shared__ __half As[BM][24];      // [m][k], pad to 24
    __shared__ __half Bs[64][20];      // [n][k] transposed, pad to 20
    __shared__ float  Hs[BM][68];      // staged fp32 h2 tile, pad to 68

    const int tid = threadIdx.x;
    const int w   = tid >> 5;
    const int lane = tid & 31;
    const int g = lane >> 2;
    const int t = lane & 3;
    const int wm = (w & 3) * 16;       // 4 m-groups
    const int wn = (w >> 2) * 32;      // 2 n-groups
    const int m0 = blockIdx.x * BM;

    float c[4][4];                     // [n-frag][c-reg], single m-frag
    #pragma unroll
    for (int nf = 0; nf < 4; nf++)
        #pragma unroll
        for (int q = 0; q < 4; q++) c[nf][q] = 0.f;

    const int arow = tid >> 2;         // 0..63
    const int ac4  = (tid & 3) * 4;

    for (int k0 = 0; k0 < HID; k0 += 16) {
        // A tile: o1 64x16 fp32 -> fp16
        {
            float4 v = make_float4(0.f, 0.f, 0.f, 0.f);
            int gr = m0 + arow;
            if (gr < M) v = *(const float4*)(A + (size_t)gr * HID + k0 + ac4);
            *(__half2*)&As[arow][ac4]     = __floats2half2_rn(v.x, v.y);
            *(__half2*)&As[arow][ac4 + 2] = __floats2half2_rn(v.z, v.w);
        }
        // B tile: W2[k0..k0+16][0..64] -> Bs[n][k] fp16; 16x16 float4 = 256 loads
        {
            int kk = tid >> 4;          // 0..15
            int n4 = (tid & 15) * 4;    // 0..60
            float4 wv = *(const float4*)(W + (size_t)(k0 + kk) * OUTD + n4);
            Bs[n4 + 0][kk] = __float2half_rn(wv.x);
            Bs[n4 + 1][kk] = __float2half_rn(wv.y);
            Bs[n4 + 2][kk] = __float2half_rn(wv.z);
            Bs[n4 + 3][kk] = __float2half_rn(wv.w);
        }
        __syncthreads();

        unsigned a[4];
        a[0] = *(const unsigned*)&As[wm + g][2 * t];
        a[1] = *(const unsigned*)&As[wm + 8 + g][2 * t];
        a[2] = *(const unsigned*)&As[wm + g][2 * t + 8];
        a[3] = *(const unsigned*)&As[wm + 8 + g][2 * t + 8];
        #pragma unroll
        for (int nf = 0; nf < 4; nf++) {
            int n = wn + nf * 8;
            unsigned b0 = *(const unsigned*)&Bs[n + g][2 * t];
            unsigned b1 = *(const unsigned*)&Bs[n + g][2 * t + 8];
            asm volatile(
                "mma.sync.aligned.m16n8k16.row.col.f32.f16.f16.f32 "
                "{%0,%1,%2,%3}, {%4,%5,%6,%7}, {%8,%9}, {%0,%1,%2,%3};"
                : "+f"(c[nf][0]), "+f"(c[nf][1]), "+f"(c[nf][2]), "+f"(c[nf][3])
                : "r"(a[0]), "r"(a[1]), "r"(a[2]), "r"(a[3]),
                  "r"(b0), "r"(b1));
        }
        __syncthreads();
    }

    // stage fp32 accums
    #pragma unroll
    for (int nf = 0; nf < 4; nf++) {
        int cc = wn + nf * 8 + 2 * t;
        Hs[wm + g][cc]     = c[nf][0];
        Hs[wm + g][cc + 1] = c[nf][1];
        Hs[wm + 8 + g][cc]     = c[nf][2];
        Hs[wm + 8 + g][cc + 1] = c[nf][3];
    }
    __syncthreads();

    // h2 store: 64 rows x 64 floats, coalesced float4 (64x16 = 1024 stores)
    #pragma unroll
    for (int i = tid; i < 64 * 16; i += 256) {
        int row = i >> 4, seg = (i & 15) * 4;
        if (m0 + row < M) {
            float4 v = *(const float4*)&Hs[row][seg];
            *(float4*)(Hout + (size_t)(m0 + row) * OUTD + seg) = v;
        }
    }

    // fused scores (64-dim): warp w handles rows w*8..w*8+7, float2 per lane
    float2 a1v = *(const float2*)(asrc + lane * 2);
    float2 a2v = *(const float2*)(adst + lane * 2);
    #pragma unroll
    for (int r = 0; r < 8; r++) {
        int row = w * 8 + r;
        float2 hv = *(const float2*)&Hs[row][lane * 2];
        float d1 = hv.x * a1v.x + hv.y * a1v.y;
        float d2 = hv.x * a2v.x + hv.y * a2v.y;
        #pragma unroll
        for (int o = 16; o; o >>= 1) {
            d1 += __shfl_xor_sync(FULLM, d1, o);
            d2 += __shfl_xor_sync(FULLM, d2, o);
        }
        if (lane == 0 && m0 + row < M) {
            ssrc[m0 + row] = d1;
            sdst[m0 + row] = d2;
        }
    }
}

// ---------------- layer-1 agg: online-softmax, fp16 h gathers (verbatim) ----------------
__global__ void k_aggH(const __half* __restrict__ h,
                       const float* __restrict__ ssrc, const float* __restrict__ sdst,
                       const float* __restrict__ bias, float* __restrict__ out) {
    int node = (blockIdx.x * blockDim.x + threadIdx.x) >> 5;
    if (node >= N_NODES) return;
    int lane = threadIdx.x & 31;
    int beg = g_off[node], end = g_off[node + 1];
    float sd = sdst[node];

    float m = -FLT_MAX, s = 0.f;
    float acc0 = 0.f, acc1 = 0.f, acc2 = 0.f, acc3 = 0.f;

    for (int c0 = beg; c0 < end; c0 += 32) {
        int n = min(32, end - c0);
        float e = -FLT_MAX; int cs = 0;
        if (lane < n) {
            cs = g_col[c0 + lane];
            float t = ssrc[cs] + sd;
            e = (t > 0.f) ? t : NEG_SLOPE * t;
        }
        float cm = e;
        #pragma unroll
        for (int o = 16; o; o >>= 1) cm = fmaxf(cm, __shfl_xor_sync(FULLM, cm, o));
        float mn = fmaxf(m, cm);
        float scale = __expf(m - mn);
        s *= scale;
        acc0 *= scale; acc1 *= scale; acc2 *= scale; acc3 *= scale;

        float w = (lane < n) ? __expf(e - mn) : 0.f;
        float ws = w;
        #pragma unroll
        for (int o = 16; o; o >>= 1) ws += __shfl_xor_sync(FULLM, ws, o);
        s += ws;
        m = mn;

        int k = 0;
        for (; k + 4 <= n; k += 4) {
            float w0 = __shfl_sync(FULLM, w, k);
            float w1 = __shfl_sync(FULLM, w, k + 1);
            float w2 = __shfl_sync(FULLM, w, k + 2);
            float w3 = __shfl_sync(FULLM, w, k + 3);
            int s0 = __shfl_sync(FULLM, cs, k);
            int s1 = __shfl_sync(FULLM, cs, k + 1);
            int s2 = __shfl_sync(FULLM, cs, k + 2);
            int s3 = __shfl_sync(FULLM, cs, k + 3);
            uint2 r0 = *(const uint2*)(h + (size_t)s0 * HID + lane * 4);
            uint2 r1 = *(const uint2*)(h + (size_t)s1 * HID + lane * 4);
            uint2 r2 = *(const uint2*)(h + (size_t)s2 * HID + lane * 4);
            uint2 r3 = *(const uint2*)(h + (size_t)s3 * HID + lane * 4);
            const __half* p0 = reinterpret_cast<const __half*>(&r0);
            const __half* p1 = reinterpret_cast<const __half*>(&r1);
            const __half* p2 = reinterpret_cast<const __half*>(&r2);
            const __half* p3 = reinterpret_cast<const __half*>(&r3);
            acc0 = fmaf(w0, __half2float(p0[0]), acc0);
            acc1 = fmaf(w0, __half2float(p0[1]), acc1);
            acc2 = fmaf(w0, __half2float(p0[2]), acc2);
            acc3 = fmaf(w0, __half2float(p0[3]), acc3);
            acc0 = fmaf(w1, __half2float(p1[0]), acc0);
            acc1 = fmaf(w1, __half2float(p1[1]), acc1);
            acc2 = fmaf(w1, __half2float(p1[2]), acc2);
            acc3 = fmaf(w1, __half2float(p1[3]), acc3);
            acc0 = fmaf(w2, __half2float(p2[0]), acc0);
            acc1 = fmaf(w2, __half2float(p2[1]), acc1);
            acc2 = fmaf(w2, __half2float(p2[2]), acc2);
            acc3 = fmaf(w2, __half2float(p2[3]), acc3);
            acc0 = fmaf(w3, __half2float(p3[0]), acc0);
            acc1 = fmaf(w3, __half2float(p3[1]), acc1);
            acc2 = fmaf(w3, __half2float(p3[2]), acc2);
            acc3 = fmaf(w3, __half2float(p3[3]), acc3);
        }
        for (; k < n; k++) {
            float w0 = __shfl_sync(FULLM, w, k);
            int s0 = __shfl_sync(FULLM, cs, k);
            uint2 r0 = *(const uint2*)(h + (size_t)s0 * HID + lane * 4);
            const __half* p0 = reinterpret_cast<const __half*>(&r0);
            acc0 = fmaf(w0, __half2float(p0[0]), acc0);
            acc1 = fmaf(w0, __half2float(p0[1]), acc1);
            acc2 = fmaf(w0, __half2float(p0[2]), acc2);
            acc3 = fmaf(w0, __half2float(p0[3]), acc3);
        }
    }

    float inv = 1.f / s;
    float4 bv = *(const float4*)(bias + lane * 4);
    float r0 = acc0 * inv + bv.x;
    float r1 = acc1 * inv + bv.y;
    float r2 = acc2 * inv + bv.z;
    float r3 = acc3 * inv + bv.w;
    r0 = (r0 > 0.f) ? r0 : expm1f(r0);
    r1 = (r1 > 0.f) ? r1 : expm1f(r1);
    r2 = (r2 > 0.f) ? r2 : expm1f(r2);
    r3 = (r3 > 0.f) ? r3 : expm1f(r3);
    float4 o4 = make_float4(r0, r1, r2, r3);
    *(float4*)(out + (size_t)node * HID + lane * 4) = o4;
}

// ---------------- layer-2 agg: verbatim online-softmax (fp32, F=64) ----------------
__global__ void k_agg64(const float* __restrict__ h,
                        const float* __restrict__ ssrc, const float* __restrict__ sdst,
                        const float* __restrict__ bias, float* __restrict__ out) {
    int node = (blockIdx.x * blockDim.x + threadIdx.x) >> 5;
    if (node >= N_NODES) return;
    int lane = threadIdx.x & 31;
    int beg = g_off[node], end = g_off[node + 1];
    float sd = sdst[node];

    float m = -FLT_MAX, s = 0.f;
    float acc0 = 0.f, acc1 = 0.f;

    for (int c0 = beg; c0 < end; c0 += 32) {
        int n = min(32, end - c0);
        float e = -FLT_MAX; int cs = 0;
        if (lane < n) {
            cs = g_col[c0 + lane];
            float t = ssrc[cs] + sd;
            e = (t > 0.f) ? t : NEG_SLOPE * t;
        }
        float cm = e;
        #pragma unroll
        for (int o = 16; o; o >>= 1) cm = fmaxf(cm, __shfl_xor_sync(FULLM, cm, o));
        float mn = fmaxf(m, cm);
        float scale = __expf(m - mn);
        s *= scale;
        acc0 *= scale; acc1 *= scale;

        float w = (lane < n) ? __expf(e - mn) : 0.f;
        float ws = w;
        #pragma unroll
        for (int o = 16; o; o >>= 1) ws += __shfl_xor_sync(FULLM, ws, o);
        s += ws;
        m = mn;

        int k = 0;
        for (; k + 4 <= n; k += 4) {
            float w0 = __shfl_sync(FULLM, w, k);
            float w1 = __shfl_sync(FULLM, w, k + 1);
            float w2 = __shfl_sync(FULLM, w, k + 2);
            float w3 = __shfl_sync(FULLM, w, k + 3);
            int s0 = __shfl_sync(FULLM, cs, k);
            int s1 = __shfl_sync(FULLM, cs, k + 1);
            int s2 = __shfl_sync(FULLM, cs, k + 2);
            int s3 = __shfl_sync(FULLM, cs, k + 3);
            float2 v0 = *(const float2*)(h + (size_t)s0 * OUTD + lane * 2);
            float2 v1 = *(const float2*)(h + (size_t)s1 * OUTD + lane * 2);
            float2 v2 = *(const float2*)(h + (size_t)s2 * OUTD + lane * 2);
            float2 v3 = *(const float2*)(h + (size_t)s3 * OUTD + lane * 2);
            acc0 = fmaf(w0, v0.x, acc0); acc1 = fmaf(w0, v0.y, acc1);
            acc0 = fmaf(w1, v1.x, acc0); acc1 = fmaf(w1, v1.y, acc1);
            acc0 = fmaf(w2, v2.x, acc0); acc1 = fmaf(w2, v2.y, acc1);
            acc0 = fmaf(w3, v3.x, acc0); acc1 = fmaf(w3, v3.y, acc1);
        }
        for (; k < n; k++) {
            float w0 = __shfl_sync(FULLM, w, k);
            int s0 = __shfl_sync(FULLM, cs, k);
            float2 v0 = *(const float2*)(h + (size_t)s0 * OUTD + lane * 2);
            acc0 = fmaf(w0, v0.x, acc0); acc1 = fmaf(w0, v0.y, acc1);
        }
    }

    float inv = 1.f / s;
    float2 bv = *(const float2*)(bias + lane * 2);
    float2 o2 = make_float2(acc0 * inv + bv.x, acc1 * inv + bv.y);
    *(float2*)(out + (size_t)node * OUTD + lane * 2) = o2;
}

// ---------------- final copy (staged result -> d_out), streaming ----------------
__global__ void k_copy(const float* __restrict__ src, float* __restrict__ dst) {
    int i = blockIdx.x * blockDim.x + threadIdx.x;
    if (i < N_NODES * (OUTD / 4)) ((float4*)dst)[i] = ((const float4*)src)[i];
}

// ---------------- launch ----------------
extern "C" void kernel_launch(void* const* d_in, const int* in_sizes, int n_in,
                              void* d_out, int out_size) {
    const float* x   = (const float*)d_in[0];
    const int*   ei  = (const int*)d_in[1];
    const float* W1  = (const float*)d_in[2];
    const float* a1s = (const float*)d_in[3];
    const float* a1d = (const float*)d_in[4];
    const float* b1  = (const float*)d_in[5];
    const float* W2  = (const float*)d_in[6];
    const float* a2s = (const float*)d_in[7];
    const float* a2d = (const float*)d_in[8];
    const float* b2  = (const float*)d_in[9];

    // d_out (device, 25.6 MB), sequential phases:
    //   1: h1 fp16 [N,128] — written by k_gemm1_mma, gathered by k_aggH
    //   2: h2 fp32 [N,64]  — written by k_gemm2_mma, gathered by k_agg64
    //   3: final output fp32 — written by k_copy
    __half* h1h = (__half*)d_out;
    float*  h2  = (float*)d_out;
    float*  out = (float*)d_out;

    const int nodeBlk = (N_NODES + 255) / 256;
    const int edgeBlk = (ETOT + 255) / 256;
    const int warpBlk = (N_NODES * 32 + 255) / 256;
    const int gBlk    = (N_NODES + 63) / 64;     // BM=64 for both mma GEMMs
    const int cpBlk   = (N_NODES * (OUTD / 4) + 255) / 256;

    k_zeroA<<<nodeBlk, 256>>>();                                             // 0
    k_count<<<edgeBlk, 256>>>(ei);                                           // 1
    k_zeroB<<<nodeBlk, 256>>>();                                             // 2
    k_gemm1_mma<<<gBlk, 256>>>(x, W1, h1h, a1s, a1d,
                               g_ssrc, g_sdst, N_NODES);                     // 3 <- ncu
    k_scan1<<<SCAN_NB, 256>>>();                                             // 4
    k_scan2<<<1, 512>>>(SCAN_NB);                                            // 5
    k_scan3<<<SCAN_NB, 256>>>();                                             // 6
    k_fill<<<edgeBlk, 256>>>(ei);                                            // 7
    k_aggH<<<warpBlk, 256>>>(h1h, g_ssrc, g_sdst, b1, g_o1);                 // 8
    k_gemm2_mma<<<gBlk, 256>>>(g_o1, W2, h2, a2s, a2d,
                               g_ssrc, g_sdst, N_NODES);                     // 9
    k_agg64<<<warpBlk, 256>>>(h2, g_ssrc, g_sdst, b2, g_o2);                 // 10
    k_copy<<<cpBlk, 256>>>(g_o2, out);                                       // 11
}

// round 13
// speedup vs baseline: 1.2666x; 1.2666x over previous
#include <cuda_runtime.h>
#include <cuda_fp16.h>
#include <math.h>
#include <float.h>

#define N_NODES 100000
#define N_EDGES 1600000
#define ETOT    (N_EDGES + N_NODES)
#define IN_DIM  256
#define HID     128
#define OUTD    64
#define NEG_SLOPE 0.2f
#define SCAN_NB ((N_NODES + 255) / 256)   // 391
#define FULLM 0xffffffffu

// ---------------- scratch (static device globals; no allocation) ----------------
// Placement law (measured R4/R9/R10/R12): random gathers from statics pay a
// 32B C2C sector @200GB/s; streams are fast. Gather tables live in d_out.
static __device__ __align__(128) float g_o1[(size_t)N_NODES * HID];   // elu(agg1+b1), streamed
static __device__ __align__(128) float g_o2[(size_t)N_NODES * OUTD];  // staged final, streamed
static __device__ float g_ssrc[N_NODES];   // written by gemm epilogues (unused by aggs now)
static __device__ float g_sdst[N_NODES];
static __device__ int   g_cnt[N_NODES];
static __device__ int   g_cur[N_NODES];
static __device__ int   g_off[N_NODES + 1];
static __device__ int   g_bsum[512];
static __device__ int   g_col[ETOT];

// ---------------- CSR build (verbatim, verified) ----------------
__global__ void k_zeroA() {
    int i = blockIdx.x * blockDim.x + threadIdx.x;
    if (i < N_NODES) g_cnt[i] = 0;
}
__global__ void k_zeroB() {
    int i = blockIdx.x * blockDim.x + threadIdx.x;
    if (i < N_NODES) g_cur[i] = 0;
}

__global__ void k_count(const int* __restrict__ ei) {
    int t = blockIdx.x * blockDim.x + threadIdx.x;
    if (t >= ETOT) return;
    int dst = (t < N_EDGES) ? ei[N_EDGES + t] : (t - N_EDGES);
    atomicAdd(&g_cnt[dst], 1);
}

__global__ void k_scan1() {
    __shared__ int s[256];
    int t = threadIdx.x, idx = blockIdx.x * 256 + t;
    int v = (idx < N_NODES) ? g_cnt[idx] : 0;
    s[t] = v; __syncthreads();
    #pragma unroll
    for (int o = 1; o < 256; o <<= 1) {
        int u = (t >= o) ? s[t - o] : 0;
        __syncthreads();
        s[t] += u;
        __syncthreads();
    }
    if (idx < N_NODES) g_off[idx] = s[t] - v;
    if (t == 255) g_bsum[blockIdx.x] = s[t];
}

__global__ void k_scan2(int nb) {
    __shared__ int s[512];
    int t = threadIdx.x;
    int v = (t < nb) ? g_bsum[t] : 0;
    s[t] = v; __syncthreads();
    #pragma unroll
    for (int o = 1; o < 512; o <<= 1) {
        int u = (t >= o) ? s[t - o] : 0;
        __syncthreads();
        s[t] += u;
        __syncthreads();
    }
    g_bsum[t] = s[t] - v;
}

__global__ void k_scan3() {
    int t = threadIdx.x, idx = blockIdx.x * 256 + t;
    if (idx < N_NODES) g_off[idx] += g_bsum[blockIdx.x];
    if (idx == 0) g_off[N_NODES] = ETOT;
}

__global__ void k_fill(const int* __restrict__ ei) {
    int t = blockIdx.x * blockDim.x + threadIdx.x;
    if (t >= ETOT) return;
    int src, dst;
    if (t < N_EDGES) { src = ei[t]; dst = ei[N_EDGES + t]; }
    else             { src = dst = t - N_EDGES; }
    int pos = g_off[dst] + atomicAdd(&g_cur[dst], 1);
    g_col[pos] = src;
}

// ---------------- tensor-core GEMM1 (verbatim, verified) ----------------
__global__ void __launch_bounds__(256) k_gemm1_mma(
        const float* __restrict__ A, const float* __restrict__ W,
        __half* __restrict__ Hout,
        const float* __restrict__ asrc, const float* __restrict__ adst,
        float* __restrict__ ssrc, float* __restrict__ sdst, int M) {
    constexpr int BM = 64;
    __shared__ __half As[BM][24];
    __shared__ __half Bs[128][20];
    __shared__ __half Hs[BM][136];

    const int tid = threadIdx.x;
    const int w   = tid >> 5;
    const int lane = tid & 31;
    const int g = lane >> 2;
    const int t = lane & 3;
    const int wm = (w & 1) * 32;
    const int wn = (w >> 1) * 32;
    const int m0 = blockIdx.x * BM;

    float c[2][4][4];
    #pragma unroll
    for (int mf = 0; mf < 2; mf++)
        #pragma unroll
        for (int nf = 0; nf < 4; nf++)
            #pragma unroll
            for (int q = 0; q < 4; q++) c[mf][nf][q] = 0.f;

    const int arow = tid >> 2;
    const int ac4  = (tid & 3) * 4;

    for (int k0 = 0; k0 < IN_DIM; k0 += 16) {
        {
            float4 v = make_float4(0.f, 0.f, 0.f, 0.f);
            int gr = m0 + arow;
            if (gr < M) v = *(const float4*)(A + (size_t)gr * IN_DIM + k0 + ac4);
            *(__half2*)&As[arow][ac4]     = __floats2half2_rn(v.x, v.y);
            *(__half2*)&As[arow][ac4 + 2] = __floats2half2_rn(v.z, v.w);
        }
        #pragma unroll
        for (int i = tid; i < 16 * 32; i += 256) {
            int kk = i >> 5;
            int n4 = (i & 31) * 4;
            float4 wv = *(const float4*)(W + (size_t)(k0 + kk) * HID + n4);
            Bs[n4 + 0][kk] = __float2half_rn(wv.x);
            Bs[n4 + 1][kk] = __float2half_rn(wv.y);
            Bs[n4 + 2][kk] = __float2half_rn(wv.z);
            Bs[n4 + 3][kk] = __float2half_rn(wv.w);
        }
        __syncthreads();

        unsigned a[2][4];
        #pragma unroll
        for (int mf = 0; mf < 2; mf++) {
            int r = wm + mf * 16;
            a[mf][0] = *(const unsigned*)&As[r + g][2 * t];
            a[mf][1] = *(const unsigned*)&As[r + 8 + g][2 * t];
            a[mf][2] = *(const unsigned*)&As[r + g][2 * t + 8];
            a[mf][3] = *(const unsigned*)&As[r + 8 + g][2 * t + 8];
        }
        #pragma unroll
        for (int nf = 0; nf < 4; nf++) {
            int n = wn + nf * 8;
            unsigned b0 = *(const unsigned*)&Bs[n + g][2 * t];
            unsigned b1 = *(const unsigned*)&Bs[n + g][2 * t + 8];
            #pragma unroll
            for (int mf = 0; mf < 2; mf++) {
                asm volatile(
                    "mma.sync.aligned.m16n8k16.row.col.f32.f16.f16.f32 "
                    "{%0,%1,%2,%3}, {%4,%5,%6,%7}, {%8,%9}, {%0,%1,%2,%3};"
                    : "+f"(c[mf][nf][0]), "+f"(c[mf][nf][1]),
                      "+f"(c[mf][nf][2]), "+f"(c[mf][nf][3])
                    : "r"(a[mf][0]), "r"(a[mf][1]), "r"(a[mf][2]), "r"(a[mf][3]),
                      "r"(b0), "r"(b1));
            }
        }
        __syncthreads();
    }

    #pragma unroll
    for (int mf = 0; mf < 2; mf++) {
        #pragma unroll
        for (int nf = 0; nf < 4; nf++) {
            int r0 = wm + mf * 16 + g;
            int cc = wn + nf * 8 + 2 * t;
            *(__half2*)&Hs[r0][cc]     = __floats2half2_rn(c[mf][nf][0], c[mf][nf][1]);
            *(__half2*)&Hs[r0 + 8][cc] = __floats2half2_rn(c[mf][nf][2], c[mf][nf][3]);
        }
    }
    __syncthreads();

    #pragma unroll
    for (int i = tid; i < 64 * 16; i += 256) {
        int row = i >> 4, seg = i & 15;
        if (m0 + row < M) {
            uint4 v = *(const uint4*)&Hs[row][seg * 8];
            *(uint4*)(Hout + (size_t)(m0 + row) * HID + seg * 8) = v;
        }
    }

    float4 a1v = *(const float4*)(asrc + lane * 4);
    float4 a2v = *(const float4*)(adst + lane * 4);
    #pragma unroll
    for (int r = 0; r < 8; r++) {
        int row = w * 8 + r;
        uint2 hv = *(const uint2*)&Hs[row][lane * 4];
        const __half* hp = reinterpret_cast<const __half*>(&hv);
        float f0 = __half2float(hp[0]), f1 = __half2float(hp[1]);
        float f2 = __half2float(hp[2]), f3 = __half2float(hp[3]);
        float d1 = f0 * a1v.x + f1 * a1v.y + f2 * a1v.z + f3 * a1v.w;
        float d2 = f0 * a2v.x + f1 * a2v.y + f2 * a2v.z + f3 * a2v.w;
        #pragma unroll
        for (int o = 16; o; o >>= 1) {
            d1 += __shfl_xor_sync(FULLM, d1, o);
            d2 += __shfl_xor_sync(FULLM, d2, o);
        }
        if (lane == 0 && m0 + row < M) {
            ssrc[m0 + row] = d1;
            sdst[m0 + row] = d2;
        }
    }
}

// ---------------- tensor-core GEMM2 (verbatim R12) ----------------
__global__ void __launch_bounds__(256) k_gemm2_mma(
        const float* __restrict__ A, const float* __restrict__ W,
        float* __restrict__ Hout,
        const float* __restrict__ asrc, const float* __restrict__ adst,
        float* __restrict__ ssrc, float* __restrict__ sdst, int M) {
    constexpr int BM = 64;
    __shared__ __half As[BM][24];
    __shared__ __half Bs[64][20];
    __shared__ float  Hs[BM][68];

    const int tid = threadIdx.x;
    const int w   = tid >> 5;
    const int lane = tid & 31;
    const int g = lane >> 2;
    const int t = lane & 3;
    const int wm = (w & 3) * 16;
    const int wn = (w >> 2) * 32;
    const int m0 = blockIdx.x * BM;

    float c[4][4];
    #pragma unroll
    for (int nf = 0; nf < 4; nf++)
        #pragma unroll
        for (int q = 0; q < 4; q++) c[nf][q] = 0.f;

    const int arow = tid >> 2;
    const int ac4  = (tid & 3) * 4;

    for (int k0 = 0; k0 < HID; k0 += 16) {
        {
            float4 v = make_float4(0.f, 0.f, 0.f, 0.f);
            int gr = m0 + arow;
            if (gr < M) v = *(const float4*)(A + (size_t)gr * HID + k0 + ac4);
            *(__half2*)&As[arow][ac4]     = __floats2half2_rn(v.x, v.y);
            *(__half2*)&As[arow][ac4 + 2] = __floats2half2_rn(v.z, v.w);
        }
        {
            int kk = tid >> 4;
            int n4 = (tid & 15) * 4;
            float4 wv = *(const float4*)(W + (size_t)(k0 + kk) * OUTD + n4);
            Bs[n4 + 0][kk] = __float2half_rn(wv.x);
            Bs[n4 + 1][kk] = __float2half_rn(wv.y);
            Bs[n4 + 2][kk] = __float2half_rn(wv.z);
            Bs[n4 + 3][kk] = __float2half_rn(wv.w);
        }
        __syncthreads();

        unsigned a[4];
        a[0] = *(const unsigned*)&As[wm + g][2 * t];
        a[1] = *(const unsigned*)&As[wm + 8 + g][2 * t];
        a[2] = *(const unsigned*)&As[wm + g][2 * t + 8];
        a[3] = *(const unsigned*)&As[wm + 8 + g][2 * t + 8];
        #pragma unroll
        for (int nf = 0; nf < 4; nf++) {
            int n = wn + nf * 8;
            unsigned b0 = *(const unsigned*)&Bs[n + g][2 * t];
            unsigned b1 = *(const unsigned*)&Bs[n + g][2 * t + 8];
            asm volatile(
                "mma.sync.aligned.m16n8k16.row.col.f32.f16.f16.f32 "
                "{%0,%1,%2,%3}, {%4,%5,%6,%7}, {%8,%9}, {%0,%1,%2,%3};"
                : "+f"(c[nf][0]), "+f"(c[nf][1]), "+f"(c[nf][2]), "+f"(c[nf][3])
                : "r"(a[0]), "r"(a[1]), "r"(a[2]), "r"(a[3]),
                  "r"(b0), "r"(b1));
        }
        __syncthreads();
    }

    #pragma unroll
    for (int nf = 0; nf < 4; nf++) {
        int cc = wn + nf * 8 + 2 * t;
        Hs[wm + g][cc]     = c[nf][0];
        Hs[wm + g][cc + 1] = c[nf][1];
        Hs[wm + 8 + g][cc]     = c[nf][2];
        Hs[wm + 8 + g][cc + 1] = c[nf][3];
    }
    __syncthreads();

    #pragma unroll
    for (int i = tid; i < 64 * 16; i += 256) {
        int row = i >> 4, seg = (i & 15) * 4;
        if (m0 + row < M) {
            float4 v = *(const float4*)&Hs[row][seg];
            *(float4*)(Hout + (size_t)(m0 + row) * OUTD + seg) = v;
        }
    }

    float2 a1v = *(const float2*)(asrc + lane * 2);
    float2 a2v = *(const float2*)(adst + lane * 2);
    #pragma unroll
    for (int r = 0; r < 8; r++) {
        int row = w * 8 + r;
        float2 hv = *(const float2*)&Hs[row][lane * 2];
        float d1 = hv.x * a1v.x + hv.y * a1v.y;
        float d2 = hv.x * a2v.x + hv.y * a2v.y;
        #pragma unroll
        for (int o = 16; o; o >>= 1) {
            d1 += __shfl_xor_sync(FULLM, d1, o);
            d2 += __shfl_xor_sync(FULLM, d2, o);
        }
        if (lane == 0 && m0 + row < M) {
            ssrc[m0 + row] = d1;
            sdst[m0 + row] = d2;
        }
    }
}

// ---------------- layer-1 agg v2: scores computed from gathered fp16 rows ----------------
// Eliminates random ssrc[] host gathers: pass-1 per chunk gathers each edge's
// h row (device L2), dots with a_src via shfl reduce; pass-2 accumulates
// (verbatim from verified kernel; rows L1/L2-hot on re-gather).
__global__ void k_aggH(const __half* __restrict__ h,
                       const float* __restrict__ asrc, const float* __restrict__ sdst,
                       const float* __restrict__ bias, float* __restrict__ out) {
    int node = (blockIdx.x * blockDim.x + threadIdx.x) >> 5;
    if (node >= N_NODES) return;
    int lane = threadIdx.x & 31;
    int beg = g_off[node], end = g_off[node + 1];
    float sd = sdst[node];
    float4 a1v = *(const float4*)(asrc + lane * 4);

    float m = -FLT_MAX, s = 0.f;
    float acc0 = 0.f, acc1 = 0.f, acc2 = 0.f, acc3 = 0.f;

    for (int c0 = beg; c0 < end; c0 += 32) {
        int n = min(32, end - c0);
        int cs = (lane < n) ? g_col[c0 + lane] : 0;

        // ---- pass 1: per-edge score e = leaky(h[cs]·a_src + sd) ----
        float e = -FLT_MAX;
        {
            int k = 0;
            for (; k + 4 <= n; k += 4) {
                int s0 = __shfl_sync(FULLM, cs, k);
                int s1 = __shfl_sync(FULLM, cs, k + 1);
                int s2 = __shfl_sync(FULLM, cs, k + 2);
                int s3 = __shfl_sync(FULLM, cs, k + 3);
                uint2 r0 = *(const uint2*)(h + (size_t)s0 * HID + lane * 4);
                uint2 r1 = *(const uint2*)(h + (size_t)s1 * HID + lane * 4);
                uint2 r2 = *(const uint2*)(h + (size_t)s2 * HID + lane * 4);
                uint2 r3 = *(const uint2*)(h + (size_t)s3 * HID + lane * 4);
                const __half* p0 = reinterpret_cast<const __half*>(&r0);
                const __half* p1 = reinterpret_cast<const __half*>(&r1);
                const __half* p2 = reinterpret_cast<const __half*>(&r2);
                const __half* p3 = reinterpret_cast<const __half*>(&r3);
                float d0 = __half2float(p0[0]) * a1v.x + __half2float(p0[1]) * a1v.y
                         + __half2float(p0[2]) * a1v.z + __half2float(p0[3]) * a1v.w;
                float d1 = __half2float(p1[0]) * a1v.x + __half2float(p1[1]) * a1v.y
                         + __half2float(p1[2]) * a1v.z + __half2float(p1[3]) * a1v.w;
                float d2 = __half2float(p2[0]) * a1v.x + __half2float(p2[1]) * a1v.y
                         + __half2float(p2[2]) * a1v.z + __half2float(p2[3]) * a1v.w;
                float d3 = __half2float(p3[0]) * a1v.x + __half2float(p3[1]) * a1v.y
                         + __half2float(p3[2]) * a1v.z + __half2float(p3[3]) * a1v.w;
                #pragma unroll
                for (int o = 16; o; o >>= 1) {
                    d0 += __shfl_xor_sync(FULLM, d0, o);
                    d1 += __shfl_xor_sync(FULLM, d1, o);
                    d2 += __shfl_xor_sync(FULLM, d2, o);
                    d3 += __shfl_xor_sync(FULLM, d3, o);
                }
                float t0 = d0 + sd, t1 = d1 + sd, t2 = d2 + sd, t3 = d3 + sd;
                t0 = (t0 > 0.f) ? t0 : NEG_SLOPE * t0;
                t1 = (t1 > 0.f) ? t1 : NEG_SLOPE * t1;
                t2 = (t2 > 0.f) ? t2 : NEG_SLOPE * t2;
                t3 = (t3 > 0.f) ? t3 : NEG_SLOPE * t3;
                if (lane == k)     e = t0;
                if (lane == k + 1) e = t1;
                if (lane == k + 2) e = t2;
                if (lane == k + 3) e = t3;
            }
            for (; k < n; k++) {
                int s0 = __shfl_sync(FULLM, cs, k);
                uint2 r0 = *(const uint2*)(h + (size_t)s0 * HID + lane * 4);
                const __half* p0 = reinterpret_cast<const __half*>(&r0);
                float d0 = __half2float(p0[0]) * a1v.x + __half2float(p0[1]) * a1v.y
                         + __half2float(p0[2]) * a1v.z + __half2float(p0[3]) * a1v.w;
                #pragma unroll
                for (int o = 16; o; o >>= 1) d0 += __shfl_xor_sync(FULLM, d0, o);
                float t0 = d0 + sd;
                t0 = (t0 > 0.f) ? t0 : NEG_SLOPE * t0;
                if (lane == k) e = t0;
            }
        }

        // ---- online-softmax bookkeeping (verbatim) ----
        float cm = e;
        #pragma unroll
        for (int o = 16; o; o >>= 1) cm = fmaxf(cm, __shfl_xor_sync(FULLM, cm, o));
        float mn = fmaxf(m, cm);
        float scale = __expf(m - mn);
        s *= scale;
        acc0 *= scale; acc1 *= scale; acc2 *= scale; acc3 *= scale;

        float w = (lane < n) ? __expf(e - mn) : 0.f;
        float ws = w;
        #pragma unroll
        for (int o = 16; o; o >>= 1) ws += __shfl_xor_sync(FULLM, ws, o);
        s += ws;
        m = mn;

        // ---- pass 2: accumulate (verbatim; rows are cache-hot) ----
        int k = 0;
        for (; k + 4 <= n; k += 4) {
            float w0 = __shfl_sync(FULLM, w, k);
            float w1 = __shfl_sync(FULLM, w, k + 1);
            float w2 = __shfl_sync(FULLM, w, k + 2);
            float w3 = __shfl_sync(FULLM, w, k + 3);
            int s0 = __shfl_sync(FULLM, cs, k);
            int s1 = __shfl_sync(FULLM, cs, k + 1);
            int s2 = __shfl_sync(FULLM, cs, k + 2);
            int s3 = __shfl_sync(FULLM, cs, k + 3);
            uint2 r0 = *(const uint2*)(h + (size_t)s0 * HID + lane * 4);
            uint2 r1 = *(const uint2*)(h + (size_t)s1 * HID + lane * 4);
            uint2 r2 = *(const uint2*)(h + (size_t)s2 * HID + lane * 4);
            uint2 r3 = *(const uint2*)(h + (size_t)s3 * HID + lane * 4);
            const __half* p0 = reinterpret_cast<const __half*>(&r0);
            const __half* p1 = reinterpret_cast<const __half*>(&r1);
            const __half* p2 = reinterpret_cast<const __half*>(&r2);
            const __half* p3 = reinterpret_cast<const __half*>(&r3);
            acc0 = fmaf(w0, __half2float(p0[0]), acc0);
            acc1 = fmaf(w0, __half2float(p0[1]), acc1);
            acc2 = fmaf(w0, __half2float(p0[2]), acc2);
            acc3 = fmaf(w0, __half2float(p0[3]), acc3);
            acc0 = fmaf(w1, __half2float(p1[0]), acc0);
            acc1 = fmaf(w1, __half2float(p1[1]), acc1);
            acc2 = fmaf(w1, __half2float(p1[2]), acc2);
            acc3 = fmaf(w1, __half2float(p1[3]), acc3);
            acc0 = fmaf(w2, __half2float(p2[0]), acc0);
            acc1 = fmaf(w2, __half2float(p2[1]), acc1);
            acc2 = fmaf(w2, __half2float(p2[2]), acc2);
            acc3 = fmaf(w2, __half2float(p2[3]), acc3);
            acc0 = fmaf(w3, __half2float(p3[0]), acc0);
            acc1 = fmaf(w3, __half2float(p3[1]), acc1);
            acc2 = fmaf(w3, __half2float(p3[2]), acc2);
            acc3 = fmaf(w3, __half2float(p3[3]), acc3);
        }
        for (; k < n; k++) {
            float w0 = __shfl_sync(FULLM, w, k);
            int s0 = __shfl_sync(FULLM, cs, k);
            uint2 r0 = *(const uint2*)(h + (size_t)s0 * HID + lane * 4);
            const __half* p0 = reinterpret_cast<const __half*>(&r0);
            acc0 = fmaf(w0, __half2float(p0[0]), acc0);
            acc1 = fmaf(w0, __half2float(p0[1]), acc1);
            acc2 = fmaf(w0, __half2float(p0[2]), acc2);
            acc3 = fmaf(w0, __half2float(p0[3]), acc3);
        }
    }

    float inv = 1.f / s;
    float4 bv = *(const float4*)(bias + lane * 4);
    float r0 = acc0 * inv + bv.x;
    float r1 = acc1 * inv + bv.y;
    float r2 = acc2 * inv + bv.z;
    float r3 = acc3 * inv + bv.w;
    r0 = (r0 > 0.f) ? r0 : expm1f(r0);
    r1 = (r1 > 0.f) ? r1 : expm1f(r1);
    r2 = (r2 > 0.f) ? r2 : expm1f(r2);
    r3 = (r3 > 0.f) ? r3 : expm1f(r3);
    float4 o4 = make_float4(r0, r1, r2, r3);
    *(float4*)(out + (size_t)node * HID + lane * 4) = o4;
}

// ---------------- layer-2 agg v2: scores from gathered fp32 rows ----------------
__global__ void k_agg64(const float* __restrict__ h,
                        const float* __restrict__ asrc, const float* __restrict__ sdst,
                        const float* __restrict__ bias, float* __restrict__ out) {
    int node = (blockIdx.x * blockDim.x + threadIdx.x) >> 5;
    if (node >= N_NODES) return;
    int lane = threadIdx.x & 31;
    int beg = g_off[node], end = g_off[node + 1];
    float sd = sdst[node];
    float2 a1v = *(const float2*)(asrc + lane * 2);

    float m = -FLT_MAX, s = 0.f;
    float acc0 = 0.f, acc1 = 0.f;

    for (int c0 = beg; c0 < end; c0 += 32) {
        int n = min(32, end - c0);
        int cs = (lane < n) ? g_col[c0 + lane] : 0;

        // ---- pass 1: per-edge score ----
        float e = -FLT_MAX;
        {
            int k = 0;
            for (; k + 4 <= n; k += 4) {
                int s0 = __shfl_sync(FULLM, cs, k);
                int s1 = __shfl_sync(FULLM, cs, k + 1);
                int s2 = __shfl_sync(FULLM, cs, k + 2);
                int s3 = __shfl_sync(FULLM, cs, k + 3);
                float2 v0 = *(const float2*)(h + (size_t)s0 * OUTD + lane * 2);
                float2 v1 = *(const float2*)(h + (size_t)s1 * OUTD + lane * 2);
                float2 v2 = *(const float2*)(h + (size_t)s2 * OUTD + lane * 2);
                float2 v3 = *(const float2*)(h + (size_t)s3 * OUTD + lane * 2);
                float d0 = v0.x * a1v.x + v0.y * a1v.y;
                float d1 = v1.x * a1v.x + v1.y * a1v.y;
                float d2 = v2.x * a1v.x + v2.y * a1v.y;
                float d3 = v3.x * a1v.x + v3.y * a1v.y;
                #pragma unroll
                for (int o = 16; o; o >>= 1) {
                    d0 += __shfl_xor_sync(FULLM, d0, o);
                    d1 += __shfl_xor_sync(FULLM, d1, o);
                    d2 += __shfl_xor_sync(FULLM, d2, o);
                    d3 += __shfl_xor_sync(FULLM, d3, o);
                }
                float t0 = d0 + sd, t1 = d1 + sd, t2 = d2 + sd, t3 = d3 + sd;
                t0 = (t0 > 0.f) ? t0 : NEG_SLOPE * t0;
                t1 = (t1 > 0.f) ? t1 : NEG_SLOPE * t1;
                t2 = (t2 > 0.f) ? t2 : NEG_SLOPE * t2;
                t3 = (t3 > 0.f) ? t3 : NEG_SLOPE * t3;
                if (lane == k)     e = t0;
                if (lane == k + 1) e = t1;
                if (lane == k + 2) e = t2;
                if (lane == k + 3) e = t3;
            }
            for (; k < n; k++) {
                int s0 = __shfl_sync(FULLM, cs, k);
                float2 v0 = *(const float2*)(h + (size_t)s0 * OUTD + lane * 2);
                float d0 = v0.x * a1v.x + v0.y * a1v.y;
                #pragma unroll
                for (int o = 16; o; o >>= 1) d0 += __shfl_xor_sync(FULLM, d0, o);
                float t0 = d0 + sd;
                t0 = (t0 > 0.f) ? t0 : NEG_SLOPE * t0;
                if (lane == k) e = t0;
            }
        }

        float cm = e;
        #pragma unroll
        for (int o = 16; o; o >>= 1) cm = fmaxf(cm, __shfl_xor_sync(FULLM, cm, o));
        float mn = fmaxf(m, cm);
        float scale = __expf(m - mn);
        s *= scale;
        acc0 *= scale; acc1 *= scale;

        float w = (lane < n) ? __expf(e - mn) : 0.f;
        float ws = w;
        #pragma unroll
        for (int o = 16; o; o >>= 1) ws += __shfl_xor_sync(FULLM, ws, o);
        s += ws;
        m = mn;

        // ---- pass 2: accumulate (verbatim) ----
        int k = 0;
        for (; k + 4 <= n; k += 4) {
            float w0 = __shfl_sync(FULLM, w, k);
            float w1 = __shfl_sync(FULLM, w, k + 1);
            float w2 = __shfl_sync(FULLM, w, k + 2);
            float w3 = __shfl_sync(FULLM, w, k + 3);
            int s0 = __shfl_sync(FULLM, cs, k);
            int s1 = __shfl_sync(FULLM, cs, k + 1);
            int s2 = __shfl_sync(FULLM, cs, k + 2);
            int s3 = __shfl_sync(FULLM, cs, k + 3);
            float2 v0 = *(const float2*)(h + (size_t)s0 * OUTD + lane * 2);
            float2 v1 = *(const float2*)(h + (size_t)s1 * OUTD + lane * 2);
            float2 v2 = *(const float2*)(h + (size_t)s2 * OUTD + lane * 2);
            float2 v3 = *(const float2*)(h + (size_t)s3 * OUTD + lane * 2);
            acc0 = fmaf(w0, v0.x, acc0); acc1 = fmaf(w0, v0.y, acc1);
            acc0 = fmaf(w1, v1.x, acc0); acc1 = fmaf(w1, v1.y, acc1);
            acc0 = fmaf(w2, v2.x, acc0); acc1 = fmaf(w2, v2.y, acc1);
            acc0 = fmaf(w3, v3.x, acc0); acc1 = fmaf(w3, v3.y, acc1);
        }
        for (; k < n; k++) {
            float w0 = __shfl_sync(FULLM, w, k);
            int s0 = __shfl_sync(FULLM, cs, k);
            float2 v0 = *(const float2*)(h + (size_t)s0 * OUTD + lane * 2);
            acc0 = fmaf(w0, v0.x, acc0); acc1 = fmaf(w0, v0.y, acc1);
        }
    }

    float inv = 1.f / s;
    float2 bv = *(const float2*)(bias + lane * 2);
    float2 o2 = make_float2(acc0 * inv + bv.x, acc1 * inv + bv.y);
    *(float2*)(out + (size_t)node * OUTD + lane * 2) = o2;
}

// ---------------- final copy (staged result -> d_out), streaming ----------------
__global__ void k_copy(const float* __restrict__ src, float* __restrict__ dst) {
    int i = blockIdx.x * blockDim.x + threadIdx.x;
    if (i < N_NODES * (OUTD / 4)) ((float4*)dst)[i] = ((const float4*)src)[i];
}

// ---------------- launch ----------------
extern "C" void kernel_launch(void* const* d_in, const int* in_sizes, int n_in,
                              void* d_out, int out_size) {
    const float* x   = (const float*)d_in[0];
    const int*   ei  = (const int*)d_in[1];
    const float* W1  = (const float*)d_in[2];
    const float* a1s = (const float*)d_in[3];
    const float* a1d = (const float*)d_in[4];
    const float* b1  = (const float*)d_in[5];
    const float* W2  = (const float*)d_in[6];
    const float* a2s = (const float*)d_in[7];
    const float* a2d = (const float*)d_in[8];
    const float* b2  = (const float*)d_in[9];

    // d_out (device, 25.6 MB), sequential phases:
    //   1: h1 fp16 [N,128] — written by k_gemm1_mma, gathered by k_aggH
    //   2: h2 fp32 [N,64]  — written by k_gemm2_mma, gathered by k_agg64
    //   3: final output fp32 — written by k_copy
    __half* h1h = (__half*)d_out;
    float*  h2  = (float*)d_out;
    float*  out = (float*)d_out;

    const int nodeBlk = (N_NODES + 255) / 256;
    const int edgeBlk = (ETOT + 255) / 256;
    const int warpBlk = (N_NODES * 32 + 255) / 256;
    const int gBlk    = (N_NODES + 63) / 64;
    const int cpBlk   = (N_NODES * (OUTD / 4) + 255) / 256;

    k_zeroA<<<nodeBlk, 256>>>();                                             // 0
    k_count<<<edgeBlk, 256>>>(ei);                                           // 1
    k_zeroB<<<nodeBlk, 256>>>();                                             // 2
    k_gemm1_mma<<<gBlk, 256>>>(x, W1, h1h, a1s, a1d,
                               g_ssrc, g_sdst, N_NODES);                     // 3 <- ncu
    k_scan1<<<SCAN_NB, 256>>>();                                             // 4
    k_scan2<<<1, 512>>>(SCAN_NB);                                            // 5
    k_scan3<<<SCAN_NB, 256>>>();                                             // 6
    k_fill<<<edgeBlk, 256>>>(ei);                                            // 7
    k_aggH<<<warpBlk, 256>>>(h1h, a1s, g_sdst, b1, g_o1);                    // 8
    k_gemm2_mma<<<gBlk, 256>>>(g_o1, W2, h2, a2s, a2d,
                               g_ssrc, g_sdst, N_NODES);                     // 9
    k_agg64<<<warpBlk, 256>>>(h2, a2s, g_sdst, b2, g_o2);                    // 10
    k_copy<<<cpBlk, 256>>>(g_o2, out);                                       // 11
}

// round 14
// speedup vs baseline: 1.2676x; 1.0008x over previous
#include <cuda_runtime.h>
#include <cuda_fp16.h>
#include <math.h>
#include <float.h>

#define N_NODES 100000
#define N_EDGES 1600000
#define ETOT    (N_EDGES + N_NODES)
#define IN_DIM  256
#define HID     128
#define OUTD    64
#define NEG_SLOPE 0.2f
#define SCAN_NB ((N_NODES + 255) / 256)   // 391
#define FULLM 0xffffffffu

// ---------------- scratch (static device globals; no allocation) ----------------
// Placement law (measured): random gathers from statics pay a 32B C2C sector
// @200GB/s; streams are fast. Gather tables live in d_out (device).
static __device__ __align__(128) float g_o1[(size_t)N_NODES * HID];   // streamed
static __device__ __align__(128) float g_o2[(size_t)N_NODES * OUTD];  // streamed
static __device__ float g_ssrc[N_NODES];   // written by gemm epilogues (unused by aggs)
static __device__ float g_sdst[N_NODES];
static __device__ int   g_cnt[N_NODES];
static __device__ int   g_cur[N_NODES];
static __device__ int   g_off[N_NODES + 1];
static __device__ int   g_bsum[512];
static __device__ int   g_col[ETOT];

// ---------------- CSR build (verbatim, verified) ----------------
__global__ void k_zeroA() {
    int i = blockIdx.x * blockDim.x + threadIdx.x;
    if (i < N_NODES) g_cnt[i] = 0;
}
__global__ void k_zeroB() {
    int i = blockIdx.x * blockDim.x + threadIdx.x;
    if (i < N_NODES) g_cur[i] = 0;
}

__global__ void k_count(const int* __restrict__ ei) {
    int t = blockIdx.x * blockDim.x + threadIdx.x;
    if (t >= ETOT) return;
    int dst = (t < N_EDGES) ? ei[N_EDGES + t] : (t - N_EDGES);
    atomicAdd(&g_cnt[dst], 1);
}

__global__ void k_scan1() {
    __shared__ int s[256];
    int t = threadIdx.x, idx = blockIdx.x * 256 + t;
    int v = (idx < N_NODES) ? g_cnt[idx] : 0;
    s[t] = v; __syncthreads();
    #pragma unroll
    for (int o = 1; o < 256; o <<= 1) {
        int u = (t >= o) ? s[t - o] : 0;
        __syncthreads();
        s[t] += u;
        __syncthreads();
    }
    if (idx < N_NODES) g_off[idx] = s[t] - v;
    if (t == 255) g_bsum[blockIdx.x] = s[t];
}

__global__ void k_scan2(int nb) {
    __shared__ int s[512];
    int t = threadIdx.x;
    int v = (t < nb) ? g_bsum[t] : 0;
    s[t] = v; __syncthreads();
    #pragma unroll
    for (int o = 1; o < 512; o <<= 1) {
        int u = (t >= o) ? s[t - o] : 0;
        __syncthreads();
        s[t] += u;
        __syncthreads();
    }
    g_bsum[t] = s[t] - v;
}

__global__ void k_scan3() {
    int t = threadIdx.x, idx = blockIdx.x * 256 + t;
    if (idx < N_NODES) g_off[idx] += g_bsum[blockIdx.x];
    if (idx == 0) g_off[N_NODES] = ETOT;
}

__global__ void k_fill(const int* __restrict__ ei) {
    int t = blockIdx.x * blockDim.x + threadIdx.x;
    if (t >= ETOT) return;
    int src, dst;
    if (t < N_EDGES) { src = ei[t]; dst = ei[N_EDGES + t]; }
    else             { src = dst = t - N_EDGES; }
    int pos = g_off[dst] + atomicAdd(&g_cur[dst], 1);
    g_col[pos] = src;
}

// ---------------- tensor-core GEMM1 (verbatim, verified) ----------------
__global__ void __launch_bounds__(256) k_gemm1_mma(
        const float* __restrict__ A, const float* __restrict__ W,
        __half* __restrict__ Hout,
        const float* __restrict__ asrc, const float* __restrict__ adst,
        float* __restrict__ ssrc, float* __restrict__ sdst, int M) {
    constexpr int BM = 64;
    __shared__ __half As[BM][24];
    __shared__ __half Bs[128][20];
    __shared__ __half Hs[BM][136];

    const int tid = threadIdx.x;
    const int w   = tid >> 5;
    const int lane = tid & 31;
    const int g = lane >> 2;
    const int t = lane & 3;
    const int wm = (w & 1) * 32;
    const int wn = (w >> 1) * 32;
    const int m0 = blockIdx.x * BM;

    float c[2][4][4];
    #pragma unroll
    for (int mf = 0; mf < 2; mf++)
        #pragma unroll
        for (int nf = 0; nf < 4; nf++)
            #pragma unroll
            for (int q = 0; q < 4; q++) c[mf][nf][q] = 0.f;

    const int arow = tid >> 2;
    const int ac4  = (tid & 3) * 4;

    for (int k0 = 0; k0 < IN_DIM; k0 += 16) {
        {
            float4 v = make_float4(0.f, 0.f, 0.f, 0.f);
            int gr = m0 + arow;
            if (gr < M) v = *(const float4*)(A + (size_t)gr * IN_DIM + k0 + ac4);
            *(__half2*)&As[arow][ac4]     = __floats2half2_rn(v.x, v.y);
            *(__half2*)&As[arow][ac4 + 2] = __floats2half2_rn(v.z, v.w);
        }
        #pragma unroll
        for (int i = tid; i < 16 * 32; i += 256) {
            int kk = i >> 5;
            int n4 = (i & 31) * 4;
            float4 wv = *(const float4*)(W + (size_t)(k0 + kk) * HID + n4);
            Bs[n4 + 0][kk] = __float2half_rn(wv.x);
            Bs[n4 + 1][kk] = __float2half_rn(wv.y);
            Bs[n4 + 2][kk] = __float2half_rn(wv.z);
            Bs[n4 + 3][kk] = __float2half_rn(wv.w);
        }
        __syncthreads();

        unsigned a[2][4];
        #pragma unroll
        for (int mf = 0; mf < 2; mf++) {
            int r = wm + mf * 16;
            a[mf][0] = *(const unsigned*)&As[r + g][2 * t];
            a[mf][1] = *(const unsigned*)&As[r + 8 + g][2 * t];
            a[mf][2] = *(const unsigned*)&As[r + g][2 * t + 8];
            a[mf][3] = *(const unsigned*)&As[r + 8 + g][2 * t + 8];
        }
        #pragma unroll
        for (int nf = 0; nf < 4; nf++) {
            int n = wn + nf * 8;
            unsigned b0 = *(const unsigned*)&Bs[n + g][2 * t];
            unsigned b1 = *(const unsigned*)&Bs[n + g][2 * t + 8];
            #pragma unroll
            for (int mf = 0; mf < 2; mf++) {
                asm volatile(
                    "mma.sync.aligned.m16n8k16.row.col.f32.f16.f16.f32 "
                    "{%0,%1,%2,%3}, {%4,%5,%6,%7}, {%8,%9}, {%0,%1,%2,%3};"
                    : "+f"(c[mf][nf][0]), "+f"(c[mf][nf][1]),
                      "+f"(c[mf][nf][2]), "+f"(c[mf][nf][3])
                    : "r"(a[mf][0]), "r"(a[mf][1]), "r"(a[mf][2]), "r"(a[mf][3]),
                      "r"(b0), "r"(b1));
            }
        }
        __syncthreads();
    }

    #pragma unroll
    for (int mf = 0; mf < 2; mf++) {
        #pragma unroll
        for (int nf = 0; nf < 4; nf++) {
            int r0 = wm + mf * 16 + g;
            int cc = wn + nf * 8 + 2 * t;
            *(__half2*)&Hs[r0][cc]     = __floats2half2_rn(c[mf][nf][0], c[mf][nf][1]);
            *(__half2*)&Hs[r0 + 8][cc] = __floats2half2_rn(c[mf][nf][2], c[mf][nf][3]);
        }
    }
    __syncthreads();

    #pragma unroll
    for (int i = tid; i < 64 * 16; i += 256) {
        int row = i >> 4, seg = i & 15;
        if (m0 + row < M) {
            uint4 v = *(const uint4*)&Hs[row][seg * 8];
            *(uint4*)(Hout + (size_t)(m0 + row) * HID + seg * 8) = v;
        }
    }

    float4 a1v = *(const float4*)(asrc + lane * 4);
    float4 a2v = *(const float4*)(adst + lane * 4);
    #pragma unroll
    for (int r = 0; r < 8; r++) {
        int row = w * 8 + r;
        uint2 hv = *(const uint2*)&Hs[row][lane * 4];
        const __half* hp = reinterpret_cast<const __half*>(&hv);
        float f0 = __half2float(hp[0]), f1 = __half2float(hp[1]);
        float f2 = __half2float(hp[2]), f3 = __half2float(hp[3]);
        float d1 = f0 * a1v.x + f1 * a1v.y + f2 * a1v.z + f3 * a1v.w;
        float d2 = f0 * a2v.x + f1 * a2v.y + f2 * a2v.z + f3 * a2v.w;
        #pragma unroll
        for (int o = 16; o; o >>= 1) {
            d1 += __shfl_xor_sync(FULLM, d1, o);
            d2 += __shfl_xor_sync(FULLM, d2, o);
        }
        if (lane == 0 && m0 + row < M) {
            ssrc[m0 + row] = d1;
            sdst[m0 + row] = d2;
        }
    }
}

// ---------------- tensor-core GEMM2 (verbatim, verified) ----------------
__global__ void __launch_bounds__(256) k_gemm2_mma(
        const float* __restrict__ A, const float* __restrict__ W,
        float* __restrict__ Hout,
        const float* __restrict__ asrc, const float* __restrict__ adst,
        float* __restrict__ ssrc, float* __restrict__ sdst, int M) {
    constexpr int BM = 64;
    __shared__ __half As[BM][24];
    __shared__ __half Bs[64][20];
    __shared__ float  Hs[BM][68];

    const int tid = threadIdx.x;
    const int w   = tid >> 5;
    const int lane = tid & 31;
    const int g = lane >> 2;
    const int t = lane & 3;
    const int wm = (w & 3) * 16;
    const int wn = (w >> 2) * 32;
    const int m0 = blockIdx.x * BM;

    float c[4][4];
    #pragma unroll
    for (int nf = 0; nf < 4; nf++)
        #pragma unroll
        for (int q = 0; q < 4; q++) c[nf][q] = 0.f;

    const int arow = tid >> 2;
    const int ac4  = (tid & 3) * 4;

    for (int k0 = 0; k0 < HID; k0 += 16) {
        {
            float4 v = make_float4(0.f, 0.f, 0.f, 0.f);
            int gr = m0 + arow;
            if (gr < M) v = *(const float4*)(A + (size_t)gr * HID + k0 + ac4);
            *(__half2*)&As[arow][ac4]     = __floats2half2_rn(v.x, v.y);
            *(__half2*)&As[arow][ac4 + 2] = __floats2half2_rn(v.z, v.w);
        }
        {
            int kk = tid >> 4;
            int n4 = (tid & 15) * 4;
            float4 wv = *(const float4*)(W + (size_t)(k0 + kk) * OUTD + n4);
            Bs[n4 + 0][kk] = __float2half_rn(wv.x);
            Bs[n4 + 1][kk] = __float2half_rn(wv.y);
            Bs[n4 + 2][kk] = __float2half_rn(wv.z);
            Bs[n4 + 3][kk] = __float2half_rn(wv.w);
        }
        __syncthreads();

        unsigned a[4];
        a[0] = *(const unsigned*)&As[wm + g][2 * t];
        a[1] = *(const unsigned*)&As[wm + 8 + g][2 * t];
        a[2] = *(const unsigned*)&As[wm + g][2 * t + 8];
        a[3] = *(const unsigned*)&As[wm + 8 + g][2 * t + 8];
        #pragma unroll
        for (int nf = 0; nf < 4; nf++) {
            int n = wn + nf * 8;
            unsigned b0 = *(const unsigned*)&Bs[n + g][2 * t];
            unsigned b1 = *(const unsigned*)&Bs[n + g][2 * t + 8];
            asm volatile(
                "mma.sync.aligned.m16n8k16.row.col.f32.f16.f16.f32 "
                "{%0,%1,%2,%3}, {%4,%5,%6,%7}, {%8,%9}, {%0,%1,%2,%3};"
                : "+f"(c[nf][0]), "+f"(c[nf][1]), "+f"(c[nf][2]), "+f"(c[nf][3])
                : "r"(a[0]), "r"(a[1]), "r"(a[2]), "r"(a[3]),
                  "r"(b0), "r"(b1));
        }
        __syncthreads();
    }

    #pragma unroll
    for (int nf = 0; nf < 4; nf++) {
        int cc = wn + nf * 8 + 2 * t;
        Hs[wm + g][cc]     = c[nf][0];
        Hs[wm + g][cc + 1] = c[nf][1];
        Hs[wm + 8 + g][cc]     = c[nf][2];
        Hs[wm + 8 + g][cc + 1] = c[nf][3];
    }
    __syncthreads();

    #pragma unroll
    for (int i = tid; i < 64 * 16; i += 256) {
        int row = i >> 4, seg = (i & 15) * 4;
        if (m0 + row < M) {
            float4 v = *(const float4*)&Hs[row][seg];
            *(float4*)(Hout + (size_t)(m0 + row) * OUTD + seg) = v;
        }
    }

    float2 a1v = *(const float2*)(asrc + lane * 2);
    float2 a2v = *(const float2*)(adst + lane * 2);
    #pragma unroll
    for (int r = 0; r < 8; r++) {
        int row = w * 8 + r;
        float2 hv = *(const float2*)&Hs[row][lane * 2];
        float d1 = hv.x * a1v.x + hv.y * a1v.y;
        float d2 = hv.x * a2v.x + hv.y * a2v.y;
        #pragma unroll
        for (int o = 16; o; o >>= 1) {
            d1 += __shfl_xor_sync(FULLM, d1, o);
            d2 += __shfl_xor_sync(FULLM, d2, o);
        }
        if (lane == 0 && m0 + row < M) {
            ssrc[m0 + row] = d1;
            sdst[m0 + row] = d2;
        }
    }
}

// ---------------- layer-1 agg v3: SINGLE-PASS per-edge online softmax ----------------
// One gather per edge. Butterfly reduce leaves the dot in every lane; each
// lane accumulates its own row fragment with flash-style rescaling.
__global__ void k_aggH(const __half* __restrict__ h,
                       const float* __restrict__ asrc, const float* __restrict__ sdst,
                       const float* __restrict__ bias, float* __restrict__ out) {
    int node = (blockIdx.x * blockDim.x + threadIdx.x) >> 5;
    if (node >= N_NODES) return;
    int lane = threadIdx.x & 31;
    int beg = g_off[node], end = g_off[node + 1];
    float sd = sdst[node];
    float4 a1v = *(const float4*)(asrc + lane * 4);

    float m = -FLT_MAX, s = 0.f;
    float acc0 = 0.f, acc1 = 0.f, acc2 = 0.f, acc3 = 0.f;

    for (int c0 = beg; c0 < end; c0 += 32) {
        int n = min(32, end - c0);
        int cs = (lane < n) ? g_col[c0 + lane] : 0;

        int k = 0;
        for (; k + 4 <= n; k += 4) {
            int s0 = __shfl_sync(FULLM, cs, k);
            int s1 = __shfl_sync(FULLM, cs, k + 1);
            int s2 = __shfl_sync(FULLM, cs, k + 2);
            int s3 = __shfl_sync(FULLM, cs, k + 3);
            uint2 r0 = *(const uint2*)(h + (size_t)s0 * HID + lane * 4);
            uint2 r1 = *(const uint2*)(h + (size_t)s1 * HID + lane * 4);
            uint2 r2 = *(const uint2*)(h + (size_t)s2 * HID + lane * 4);
            uint2 r3 = *(const uint2*)(h + (size_t)s3 * HID + lane * 4);
            const __half* p0 = reinterpret_cast<const __half*>(&r0);
            const __half* p1 = reinterpret_cast<const __half*>(&r1);
            const __half* p2 = reinterpret_cast<const __half*>(&r2);
            const __half* p3 = reinterpret_cast<const __half*>(&r3);
            float f0a = __half2float(p0[0]), f0b = __half2float(p0[1]),
                  f0c = __half2float(p0[2]), f0d = __half2float(p0[3]);
            float f1a = __half2float(p1[0]), f1b = __half2float(p1[1]),
                  f1c = __half2float(p1[2]), f1d = __half2float(p1[3]);
            float f2a = __half2float(p2[0]), f2b = __half2float(p2[1]),
                  f2c = __half2float(p2[2]), f2d = __half2float(p2[3]);
            float f3a = __half2float(p3[0]), f3b = __half2float(p3[1]),
                  f3c = __half2float(p3[2]), f3d = __half2float(p3[3]);
            float d0 = f0a * a1v.x + f0b * a1v.y + f0c * a1v.z + f0d * a1v.w;
            float d1 = f1a * a1v.x + f1b * a1v.y + f1c * a1v.z + f1d * a1v.w;
            float d2 = f2a * a1v.x + f2b * a1v.y + f2c * a1v.z + f2d * a1v.w;
            float d3 = f3a * a1v.x + f3b * a1v.y + f3c * a1v.z + f3d * a1v.w;
            #pragma unroll
            for (int o = 16; o; o >>= 1) {
                d0 += __shfl_xor_sync(FULLM, d0, o);
                d1 += __shfl_xor_sync(FULLM, d1, o);
                d2 += __shfl_xor_sync(FULLM, d2, o);
                d3 += __shfl_xor_sync(FULLM, d3, o);
            }
            // online update, edge by edge (all lanes hold identical d's)
            float e, mn, sc, wt;
            e = d0 + sd; e = (e > 0.f) ? e : NEG_SLOPE * e;
            mn = fmaxf(m, e); sc = __expf(m - mn); wt = __expf(e - mn);
            s = s * sc + wt;
            acc0 = acc0 * sc + wt * f0a; acc1 = acc1 * sc + wt * f0b;
            acc2 = acc2 * sc + wt * f0c; acc3 = acc3 * sc + wt * f0d;
            m = mn;
            e = d1 + sd; e = (e > 0.f) ? e : NEG_SLOPE * e;
            mn = fmaxf(m, e); sc = __expf(m - mn); wt = __expf(e - mn);
            s = s * sc + wt;
            acc0 = acc0 * sc + wt * f1a; acc1 = acc1 * sc + wt * f1b;
            acc2 = acc2 * sc + wt * f1c; acc3 = acc3 * sc + wt * f1d;
            m = mn;
            e = d2 + sd; e = (e > 0.f) ? e : NEG_SLOPE * e;
            mn = fmaxf(m, e); sc = __expf(m - mn); wt = __expf(e - mn);
            s = s * sc + wt;
            acc0 = acc0 * sc + wt * f2a; acc1 = acc1 * sc + wt * f2b;
            acc2 = acc2 * sc + wt * f2c; acc3 = acc3 * sc + wt * f2d;
            m = mn;
            e = d3 + sd; e = (e > 0.f) ? e : NEG_SLOPE * e;
            mn = fmaxf(m, e); sc = __expf(m - mn); wt = __expf(e - mn);
            s = s * sc + wt;
            acc0 = acc0 * sc + wt * f3a; acc1 = acc1 * sc + wt * f3b;
            acc2 = acc2 * sc + wt * f3c; acc3 = acc3 * sc + wt * f3d;
            m = mn;
        }
        for (; k < n; k++) {
            int s0 = __shfl_sync(FULLM, cs, k);
            uint2 r0 = *(const uint2*)(h + (size_t)s0 * HID + lane * 4);
            const __half* p0 = reinterpret_cast<const __half*>(&r0);
            float f0a = __half2float(p0[0]), f0b = __half2float(p0[1]),
                  f0c = __half2float(p0[2]), f0d = __half2float(p0[3]);
            float d0 = f0a * a1v.x + f0b * a1v.y + f0c * a1v.z + f0d * a1v.w;
            #pragma unroll
            for (int o = 16; o; o >>= 1) d0 += __shfl_xor_sync(FULLM, d0, o);
            float e = d0 + sd; e = (e > 0.f) ? e : NEG_SLOPE * e;
            float mn = fmaxf(m, e);
            float sc = __expf(m - mn);
            float wt = __expf(e - mn);
            s = s * sc + wt;
            acc0 = acc0 * sc + wt * f0a; acc1 = acc1 * sc + wt * f0b;
            acc2 = acc2 * sc + wt * f0c; acc3 = acc3 * sc + wt * f0d;
            m = mn;
        }
    }

    float inv = 1.f / s;
    float4 bv = *(const float4*)(bias + lane * 4);
    float r0 = acc0 * inv + bv.x;
    float r1 = acc1 * inv + bv.y;
    float r2 = acc2 * inv + bv.z;
    float r3 = acc3 * inv + bv.w;
    r0 = (r0 > 0.f) ? r0 : expm1f(r0);
    r1 = (r1 > 0.f) ? r1 : expm1f(r1);
    r2 = (r2 > 0.f) ? r2 : expm1f(r2);
    r3 = (r3 > 0.f) ? r3 : expm1f(r3);
    float4 o4 = make_float4(r0, r1, r2, r3);
    *(float4*)(out + (size_t)node * HID + lane * 4) = o4;
}

// ---------------- layer-2 agg v3: single-pass (fp32 rows, F=64) ----------------
__global__ void k_agg64(const float* __restrict__ h,
                        const float* __restrict__ asrc, const float* __restrict__ sdst,
                        const float* __restrict__ bias, float* __restrict__ out) {
    int node = (blockIdx.x * blockDim.x + threadIdx.x) >> 5;
    if (node >= N_NODES) return;
    int lane = threadIdx.x & 31;
    int beg = g_off[node], end = g_off[node + 1];
    float sd = sdst[node];
    float2 a1v = *(const float2*)(asrc + lane * 2);

    float m = -FLT_MAX, s = 0.f;
    float acc0 = 0.f, acc1 = 0.f;

    for (int c0 = beg; c0 < end; c0 += 32) {
        int n = min(32, end - c0);
        int cs = (lane < n) ? g_col[c0 + lane] : 0;

        int k = 0;
        for (; k + 4 <= n; k += 4) {
            int s0 = __shfl_sync(FULLM, cs, k);
            int s1 = __shfl_sync(FULLM, cs, k + 1);
            int s2 = __shfl_sync(FULLM, cs, k + 2);
            int s3 = __shfl_sync(FULLM, cs, k + 3);
            float2 v0 = *(const float2*)(h + (size_t)s0 * OUTD + lane * 2);
            float2 v1 = *(const float2*)(h + (size_t)s1 * OUTD + lane * 2);
            float2 v2 = *(const float2*)(h + (size_t)s2 * OUTD + lane * 2);
            float2 v3 = *(const float2*)(h + (size_t)s3 * OUTD + lane * 2);
            float d0 = v0.x * a1v.x + v0.y * a1v.y;
            float d1 = v1.x * a1v.x + v1.y * a1v.y;
            float d2 = v2.x * a1v.x + v2.y * a1v.y;
            float d3 = v3.x * a1v.x + v3.y * a1v.y;
            #pragma unroll
            for (int o = 16; o; o >>= 1) {
                d0 += __shfl_xor_sync(FULLM, d0, o);
                d1 += __shfl_xor_sync(FULLM, d1, o);
                d2 += __shfl_xor_sync(FULLM, d2, o);
                d3 += __shfl_xor_sync(FULLM, d3, o);
            }
            float e, mn, sc, wt;
            e = d0 + sd; e = (e > 0.f) ? e : NEG_SLOPE * e;
            mn = fmaxf(m, e); sc = __expf(m - mn); wt = __expf(e - mn);
            s = s * sc + wt;
            acc0 = acc0 * sc + wt * v0.x; acc1 = acc1 * sc + wt * v0.y;
            m = mn;
            e = d1 + sd; e = (e > 0.f) ? e : NEG_SLOPE * e;
            mn = fmaxf(m, e); sc = __expf(m - mn); wt = __expf(e - mn);
            s = s * sc + wt;
            acc0 = acc0 * sc + wt * v1.x; acc1 = acc1 * sc + wt * v1.y;
            m = mn;
            e = d2 + sd; e = (e > 0.f) ? e : NEG_SLOPE * e;
            mn = fmaxf(m, e); sc = __expf(m - mn); wt = __expf(e - mn);
            s = s * sc + wt;
            acc0 = acc0 * sc + wt * v2.x; acc1 = acc1 * sc + wt * v2.y;
            m = mn;
            e = d3 + sd; e = (e > 0.f) ? e : NEG_SLOPE * e;
            mn = fmaxf(m, e); sc = __expf(m - mn); wt = __expf(e - mn);
            s = s * sc + wt;
            acc0 = acc0 * sc + wt * v3.x; acc1 = acc1 * sc + wt * v3.y;
            m = mn;
        }
        for (; k < n; k++) {
            int s0 = __shfl_sync(FULLM, cs, k);
            float2 v0 = *(const float2*)(h + (size_t)s0 * OUTD + lane * 2);
            float d0 = v0.x * a1v.x + v0.y * a1v.y;
            #pragma unroll
            for (int o = 16; o; o >>= 1) d0 += __shfl_xor_sync(FULLM, d0, o);
            float e = d0 + sd; e = (e > 0.f) ? e : NEG_SLOPE * e;
            float mn = fmaxf(m, e);
            float sc = __expf(m - mn);
            float wt = __expf(e - mn);
            s = s * sc + wt;
            acc0 = acc0 * sc + wt * v0.x; acc1 = acc1 * sc + wt * v0.y;
            m = mn;
        }
    }

    float inv = 1.f / s;
    float2 bv = *(const float2*)(bias + lane * 2);
    float2 o2 = make_float2(acc0 * inv + bv.x, acc1 * inv + bv.y);
    *(float2*)(out + (size_t)node * OUTD + lane * 2) = o2;
}

// ---------------- final copy (staged result -> d_out), streaming ----------------
__global__ void k_copy(const float* __restrict__ src, float* __restrict__ dst) {
    int i = blockIdx.x * blockDim.x + threadIdx.x;
    if (i < N_NODES * (OUTD / 4)) ((float4*)dst)[i] = ((const float4*)src)[i];
}

// ---------------- launch ----------------
extern "C" void kernel_launch(void* const* d_in, const int* in_sizes, int n_in,
                              void* d_out, int out_size) {
    const float* x   = (const float*)d_in[0];
    const int*   ei  = (const int*)d_in[1];
    const float* W1  = (const float*)d_in[2];
    const float* a1s = (const float*)d_in[3];
    const float* a1d = (const float*)d_in[4];
    const float* b1  = (const float*)d_in[5];
    const float* W2  = (const float*)d_in[6];
    const float* a2s = (const float*)d_in[7];
    const float* a2d = (const float*)d_in[8];
    const float* b2  = (const float*)d_in[9];

    __half* h1h = (__half*)d_out;
    float*  h2  = (float*)d_out;
    float*  out = (float*)d_out;

    const int nodeBlk = (N_NODES + 255) / 256;
    const int edgeBlk = (ETOT + 255) / 256;
    const int warpBlk = (N_NODES * 32 + 255) / 256;
    const int gBlk    = (N_NODES + 63) / 64;
    const int cpBlk   = (N_NODES * (OUTD / 4) + 255) / 256;

    k_zeroA<<<nodeBlk, 256>>>();                                             // 0
    k_count<<<edgeBlk, 256>>>(ei);                                           // 1
    k_zeroB<<<nodeBlk, 256>>>();                                             // 2
    k_gemm1_mma<<<gBlk, 256>>>(x, W1, h1h, a1s, a1d,
                               g_ssrc, g_sdst, N_NODES);                     // 3 <- ncu
    k_scan1<<<SCAN_NB, 256>>>();                                             // 4
    k_scan2<<<1, 512>>>(SCAN_NB);                                            // 5
    k_scan3<<<SCAN_NB, 256>>>();                                             // 6
    k_fill<<<edgeBlk, 256>>>(ei);                                            // 7
    k_aggH<<<warpBlk, 256>>>(h1h, a1s, g_sdst, b1, g_o1);                    // 8
    k_gemm2_mma<<<gBlk, 256>>>(g_o1, W2, h2, a2s, a2d,
                               g_ssrc, g_sdst, N_NODES);                     // 9
    k_agg64<<<warpBlk, 256>>>(h2, a2s, g_sdst, b2, g_o2);                    // 10
    k_copy<<<cpBlk, 256>>>(g_o2, out);                                       // 11
}